// round 2
// baseline (speedup 1.0000x reference)
#include <cuda_runtime.h>
#include <cstdint>
#include <cstddef>

// Problem shape
#define B_DIM 4096
#define IN_DIM 1024
#define H_DIM 1024
#define K_DIM 2048          // IN + H concatenated along K
// Tiling
#define BM 128              // batch rows per CTA
#define BH 32               // h columns per CTA
#define BN 128              // 4 gates * BH
#define BK 32               // K per stage (32 fp32)
#define STAGES 3
#define NITER (K_DIM / BK)  // 64
#define THREADS 512

// Shared memory layout
#define APITCH 36                                  // words per A row (pad 32->36, conflict-free)
#define A_BYTES (BM * APITCH * 4)                  // 18432
#define B_BYTES (BN * APITCH * 4)                  // 18432
#define STAGE_BYTES (A_BYTES + B_BYTES)            // 36864
#define SMEM_BIAS 64                               // 4*32 floats
#define SMEM_DATA 2048
#define SMEM_TOTAL (SMEM_DATA + STAGES * STAGE_BYTES)  // 112640
// Epilogue gates buffer overlays stage area
#define GPITCH 136                                 // 128 cols + 8 pad

__device__ __forceinline__ uint32_t smem_u32(const void* p) {
    uint32_t a;
    asm("{ .reg .u64 t; cvta.to.shared.u64 t, %1; cvt.u32.u64 %0, t; }" : "=r"(a) : "l"(p));
    return a;
}
__device__ __forceinline__ void cp16(uint32_t dst, const void* src) {
    asm volatile("cp.async.cg.shared.global [%0], [%1], 16;\n" :: "r"(dst), "l"(src));
}
#define CP_COMMIT() asm volatile("cp.async.commit_group;\n" ::: "memory")
#define CP_WAIT(n)  asm volatile("cp.async.wait_group %0;\n" :: "n"(n) : "memory")

__device__ __forceinline__ void mma_tf32(float* d, const uint32_t* a, const uint32_t* b) {
    asm volatile(
        "mma.sync.aligned.m16n8k8.row.col.f32.tf32.tf32.f32 "
        "{%0, %1, %2, %3}, {%4, %5, %6, %7}, {%8, %9}, {%0, %1, %2, %3};"
        : "+f"(d[0]), "+f"(d[1]), "+f"(d[2]), "+f"(d[3])
        : "r"(a[0]), "r"(a[1]), "r"(a[2]), "r"(a[3]), "r"(b[0]), "r"(b[1]));
}

__device__ __forceinline__ float sigmoidf_fast(float x) {
    return 1.0f / (1.0f + __expf(-x));
}
__device__ __forceinline__ float tanhf_fast(float x) {
    float e = __expf(2.0f * x);
    return (e - 1.0f) / (e + 1.0f);
}

__global__ void __launch_bounds__(THREADS, 1)
lstm_kernel(const float* __restrict__ x, const float* __restrict__ hprev,
            const float* __restrict__ cprev,
            const float* __restrict__ Wxi, const float* __restrict__ Whi, const float* __restrict__ bi,
            const float* __restrict__ Wxf, const float* __restrict__ Whf, const float* __restrict__ bfv,
            const float* __restrict__ Wxg, const float* __restrict__ Whg, const float* __restrict__ bg,
            const float* __restrict__ Wxo, const float* __restrict__ Who, const float* __restrict__ bo,
            float* __restrict__ out_h, float* out_h2, float* out_c)
{
    extern __shared__ char smem[];
    const uint32_t sb = smem_u32(smem);
    const int tid  = threadIdx.x;
    const int lane = tid & 31;
    const int warp = tid >> 5;
    const int g    = lane >> 2;   // group id 0..7
    const int t4   = lane & 3;    // thread-in-group 0..3
    const int wm   = warp & 3;    // warp m index (4)
    const int wn   = warp >> 2;   // warp n index (4)

    const int bid   = blockIdx.x;
    const int htile = bid & 31;   // 32 h tiles (consecutive CTAs share A rows in L2)
    const int mtile = bid >> 5;   // 32 m tiles
    const int m0 = mtile * BM;
    const int h0 = htile * BH;

    // --- bias staging ---
    if (tid < 32) {
        float* bs = (float*)(smem + SMEM_BIAS);
        bs[0 * 32 + tid] = bi[h0 + tid];
        bs[1 * 32 + tid] = bfv[h0 + tid];
        bs[2 * 32 + tid] = bg[h0 + tid];
        bs[3 * 32 + tid] = bo[h0 + tid];
    }

    // --- per-thread cp.async descriptors: 2 A chunks + 2 B chunks (16B each) ---
    const float* const Wx[4] = {Wxi, Wxf, Wxg, Wxo};
    const float* const Wh[4] = {Whi, Whf, Whg, Who};

    const float* aptr[2];
    const float* bptr[2];
    uint32_t dA[2], dB[2];
    int brow_g[2], brow_w[2];

    #pragma unroll
    for (int j = 0; j < 2; j++) {
        int id  = tid + THREADS * j;       // 0..1023
        int row = id >> 3;                 // 0..127
        int c   = id & 7;                  // 16B chunk
        aptr[j] = x + (size_t)(m0 + row) * IN_DIM + c * 4;
        dA[j]   = (uint32_t)(row * (APITCH * 4) + c * 16);
        int gate = row >> 5;
        int wrow = h0 + (row & 31);
        brow_g[j] = gate; brow_w[j] = wrow;
        bptr[j] = Wx[gate] + (size_t)wrow * IN_DIM + c * 4;
        dB[j]   = (uint32_t)(A_BYTES + row * (APITCH * 4) + c * 16);
    }

    auto issue_stage = [&](int it) {
        if (it == NITER / 2) {  // switch from x/Wx to h/Wh at k=1024
            #pragma unroll
            for (int j = 0; j < 2; j++) {
                int id  = tid + THREADS * j;
                int row = id >> 3;
                int c   = id & 7;
                aptr[j] = hprev + (size_t)(m0 + row) * H_DIM + c * 4;
                bptr[j] = Wh[brow_g[j]] + (size_t)brow_w[j] * H_DIM + c * 4;
            }
        }
        uint32_t sbase = sb + SMEM_DATA + (uint32_t)(it % STAGES) * STAGE_BYTES;
        #pragma unroll
        for (int j = 0; j < 2; j++) { cp16(sbase + dA[j], aptr[j]); aptr[j] += BK; }
        #pragma unroll
        for (int j = 0; j < 2; j++) { cp16(sbase + dB[j], bptr[j]); bptr[j] += BK; }
        CP_COMMIT();
    };

    // --- accumulators ---
    float acc[2][4][4];
    #pragma unroll
    for (int mi = 0; mi < 2; mi++)
        #pragma unroll
        for (int ni = 0; ni < 4; ni++)
            #pragma unroll
            for (int r = 0; r < 4; r++) acc[mi][ni][r] = 0.0f;

    // --- prologue ---
    issue_stage(0);
    issue_stage(1);

    // --- main loop ---
    for (int tt = 0; tt < NITER; tt++) {
        CP_WAIT(STAGES - 2);     // stage tt resident
        __syncthreads();
        if (tt + STAGES - 1 < NITER) issue_stage(tt + STAGES - 1);

        const int s = tt % STAGES;
        const uint32_t* As = (const uint32_t*)(smem + SMEM_DATA + (size_t)s * STAGE_BYTES);
        const uint32_t* Bs = As + BM * APITCH;

        #pragma unroll
        for (int kt = 0; kt < 4; kt++) {
            const int kc = kt * 8 + t4;
            uint32_t af[2][4], bf[4][2];
            #pragma unroll
            for (int mi = 0; mi < 2; mi++) {
                int r0 = wm * 32 + mi * 16 + g;
                af[mi][0] = As[r0 * APITCH + kc];
                af[mi][1] = As[(r0 + 8) * APITCH + kc];
                af[mi][2] = As[r0 * APITCH + kc + 4];
                af[mi][3] = As[(r0 + 8) * APITCH + kc + 4];
            }
            #pragma unroll
            for (int ni = 0; ni < 4; ni++) {
                int n = wn * 32 + ni * 8 + g;
                bf[ni][0] = Bs[n * APITCH + kc];
                bf[ni][1] = Bs[n * APITCH + kc + 4];
            }
            #pragma unroll
            for (int ni = 0; ni < 4; ni++)
                #pragma unroll
                for (int mi = 0; mi < 2; mi++)
                    mma_tf32(acc[mi][ni], af[mi], bf[ni]);
        }
    }
    CP_WAIT(0);
    __syncthreads();

    // --- epilogue: accums -> smem gates buffer [128][GPITCH] ---
    float* gs = (float*)(smem + SMEM_DATA);
    #pragma unroll
    for (int mi = 0; mi < 2; mi++) {
        #pragma unroll
        for (int ni = 0; ni < 4; ni++) {
            int row = wm * 32 + mi * 16 + g;
            int col = wn * 32 + ni * 8 + 2 * t4;
            *(float2*)(gs + row * GPITCH + col)       = make_float2(acc[mi][ni][0], acc[mi][ni][1]);
            *(float2*)(gs + (row + 8) * GPITCH + col) = make_float2(acc[mi][ni][2], acc[mi][ni][3]);
        }
    }
    __syncthreads();

    // --- pointwise LSTM + writes (float4 over h) ---
    const float* bs = (const float*)(smem + SMEM_BIAS);
    #pragma unroll
    for (int rep = 0; rep < 2; rep++) {
        int idx = tid + THREADS * rep;    // 0..1023
        int m  = idx >> 3;                // 0..127
        int h4 = idx & 7;                 // 0..7 (float4 over 32 h cols)
        const float* grow = gs + m * GPITCH;

        float4 zi = *(const float4*)(grow + 0 * 32 + h4 * 4);
        float4 zf = *(const float4*)(grow + 1 * 32 + h4 * 4);
        float4 zg = *(const float4*)(grow + 2 * 32 + h4 * 4);
        float4 zo = *(const float4*)(grow + 3 * 32 + h4 * 4);
        float4 vbi = *(const float4*)(bs + 0 * 32 + h4 * 4);
        float4 vbf = *(const float4*)(bs + 1 * 32 + h4 * 4);
        float4 vbg = *(const float4*)(bs + 2 * 32 + h4 * 4);
        float4 vbo = *(const float4*)(bs + 3 * 32 + h4 * 4);

        size_t go = (size_t)(m0 + m) * H_DIM + h0 + h4 * 4;
        float4 cp = *(const float4*)(cprev + go);

        float hv[4], cv[4];
        float azi[4] = {zi.x, zi.y, zi.z, zi.w};
        float azf[4] = {zf.x, zf.y, zf.z, zf.w};
        float azg[4] = {zg.x, zg.y, zg.z, zg.w};
        float azo[4] = {zo.x, zo.y, zo.z, zo.w};
        float abi[4] = {vbi.x, vbi.y, vbi.z, vbi.w};
        float abf[4] = {vbf.x, vbf.y, vbf.z, vbf.w};
        float abg[4] = {vbg.x, vbg.y, vbg.z, vbg.w};
        float abo[4] = {vbo.x, vbo.y, vbo.z, vbo.w};
        float acp[4] = {cp.x, cp.y, cp.z, cp.w};

        #pragma unroll
        for (int j = 0; j < 4; j++) {
            float ig = sigmoidf_fast(azi[j] + abi[j]);
            float fg = sigmoidf_fast(azf[j] + abf[j]);
            float gg = tanhf_fast(azg[j] + abg[j]);
            float og = sigmoidf_fast(azo[j] + abo[j]);
            cv[j] = fg * acp[j] + ig * gg;
            hv[j] = og * tanhf_fast(cv[j]);
        }
        float4 hv4 = make_float4(hv[0], hv[1], hv[2], hv[3]);
        float4 cv4 = make_float4(cv[0], cv[1], cv[2], cv[3]);
        *(float4*)(out_h + go) = hv4;
        if (out_h2) *(float4*)(out_h2 + go) = hv4;
        if (out_c)  *(float4*)(out_c + go)  = cv4;
    }
}

extern "C" void kernel_launch(void* const* d_in, const int* in_sizes, int n_in,
                              void* d_out, int out_size) {
    const float* x      = (const float*)d_in[0];
    const float* h_prev = (const float*)d_in[1];
    const float* c_prev = (const float*)d_in[2];
    const float* W_ii = (const float*)d_in[3];
    const float* W_hi = (const float*)d_in[4];
    const float* b_i  = (const float*)d_in[5];
    const float* W_if = (const float*)d_in[6];
    const float* W_hf = (const float*)d_in[7];
    const float* b_f  = (const float*)d_in[8];
    const float* W_ig = (const float*)d_in[9];
    const float* W_hg = (const float*)d_in[10];
    const float* b_g  = (const float*)d_in[11];
    const float* W_io = (const float*)d_in[12];
    const float* W_ho = (const float*)d_in[13];
    const float* b_o  = (const float*)d_in[14];

    float* out = (float*)d_out;
    const int HB = B_DIM * H_DIM;   // 4194304
    float* oh  = out;
    float* oh2 = nullptr;
    float* oc  = nullptr;
    if (out_size >= 3 * HB)      { oh2 = out + HB; oc = out + 2 * HB; }
    else if (out_size >= 2 * HB) { oc = out + HB; }

    static bool attr_set = false;
    if (!attr_set) {
        cudaFuncSetAttribute(lstm_kernel, cudaFuncAttributeMaxDynamicSharedMemorySize, SMEM_TOTAL);
        attr_set = true;
    }
    lstm_kernel<<<(B_DIM / BM) * (H_DIM / BH), THREADS, SMEM_TOTAL>>>(
        x, h_prev, c_prev,
        W_ii, W_hi, b_i,
        W_if, W_hf, b_f,
        W_ig, W_hg, b_g,
        W_io, W_ho, b_o,
        oh, oh2, oc);
}